// round 9
// baseline (speedup 1.0000x reference)
#include <cuda_runtime.h>
#include <cstdint>

// Problem constants (fixed by the dataset)
#define NMAX 100000
#define EMAX 1000000
#define HDIM 64

// ---------------- scratch (device globals; referenced BY NAME only) ------------
__device__ float4 g_A4[(size_t)NMAX * 16];     // GEMM output (pre-aggregation)
__device__ float4 g_B4[(size_t)NMAX * 16];     // fused aggregate output (post-relu h)
__device__ float  g_deg[NMAX];
__device__ float  g_dinv[NMAX];
__device__ int    g_cnt[NMAX];                 // in-degree (edges only)
__device__ int    g_rs[NMAX];                  // CSR row start
__device__ int    g_cur[NMAX];                 // fill cursors
__device__ int2   g_edges[EMAX];               // packed (src, norm-as-int) by dst
__device__ int    g_bsum[256];                 // scan block sums
__device__ float  g_logits[NMAX];
__device__ float  g_pmax[256];
__device__ float  g_gmax;
__device__ float  g_gsum;
__device__ int    g_is64;                      // edge_index dtype flag

// ---------------- dtype probe ---------------------------------------------------
// int64 indices in [0,2^31): odd int32 words (high halves) are all zero.
// int32 random indices: essentially impossible that 32 odd words are all zero.
__global__ void detect_k(const int* __restrict__ w) {
    if (threadIdx.x == 0 && blockIdx.x == 0) {
        int allz = 1;
        for (int i = 1; i < 64; i += 2)
            if (w[i] != 0) { allz = 0; break; }
        g_is64 = allz;
    }
}

__device__ __forceinline__ int load_idx(const void* ei, long long pos, int is64, int n) {
    int v = is64 ? (int)((const long long*)ei)[pos] : ((const int*)ei)[pos];
    return min(max(v, 0), n - 1);              // defensive clamp
}

// ---------------- degree / count ------------------------------------------------
__global__ void init_k(int n) {
    int i = blockIdx.x * blockDim.x + threadIdx.x;
    if (i < n) { g_deg[i] = 1.0f; g_cnt[i] = 0; }   // self-loop weight 1
}

__global__ void deg_edges_k(const void* __restrict__ ei,
                            const float* __restrict__ ew, int E, int n) {
    int e = blockIdx.x * blockDim.x + threadIdx.x;
    if (e >= E) return;
    int is64 = g_is64;
    int dst = load_idx(ei, (long long)E + e, is64, n);
    atomicAdd(&g_deg[dst], ew[e]);
    atomicAdd(&g_cnt[dst], 1);
}

__global__ void dinv_k(int n) {
    int i = blockIdx.x * blockDim.x + threadIdx.x;
    if (i >= n) return;
    float d = g_deg[i];
    g_dinv[i] = (d > 0.0f) ? rsqrtf(d) : 0.0f;
}

// ---------------- prefix sum (CSR offsets) -------------------------------------
__global__ void scan1_k(int n) {                 // per-block exclusive scan (1024)
    __shared__ int s[1024];
    int i = blockIdx.x * 1024 + threadIdx.x;
    int v = (i < n) ? g_cnt[i] : 0;
    s[threadIdx.x] = v; __syncthreads();
#pragma unroll
    for (int o = 1; o < 1024; o <<= 1) {
        int t = (threadIdx.x >= o) ? s[threadIdx.x - o] : 0;
        __syncthreads();
        s[threadIdx.x] += t;
        __syncthreads();
    }
    if (i < n) g_rs[i] = s[threadIdx.x] - v;     // exclusive
    if (threadIdx.x == 1023) g_bsum[blockIdx.x] = s[1023];
}

__global__ void scan2_k(int nb) {                // serial scan of <=256 block sums
    if (threadIdx.x == 0) {
        int a = 0;
        for (int b = 0; b < nb; b++) { int t = g_bsum[b]; g_bsum[b] = a; a += t; }
    }
}

__global__ void scan3_k(int n) {
    int i = blockIdx.x * blockDim.x + threadIdx.x;
    if (i >= n) return;
    int r = g_rs[i] + g_bsum[i >> 10];
    g_rs[i] = r;
    g_cur[i] = r;
}

// ---------------- bucket edges by dst with precomputed norm --------------------
__global__ void fill_k(const void* __restrict__ ei,
                       const float* __restrict__ ew, int E, int n) {
    int e = blockIdx.x * blockDim.x + threadIdx.x;
    if (e >= E) return;
    int is64 = g_is64;
    int src = load_idx(ei, e, is64, n);
    int dst = load_idx(ei, (long long)E + e, is64, n);
    float norm = g_dinv[src] * ew[e] * g_dinv[dst];
    int pos = atomicAdd(&g_cur[dst], 1);
    if (pos < EMAX) g_edges[pos] = make_int2(src, __float_as_int(norm));
}

// ---------------- GEMM: g_A4[n,64] = X[n,64] @ W[64,64] ------------------------
// FROM_B=false: X = input param. FROM_B=true: X = g_B4 (layer-2 hidden state).
#define GROWS 32
template <bool FROM_B>
__global__ __launch_bounds__(256) void gemm_k(const float* __restrict__ Xin,
                                              const float* __restrict__ W, int n) {
    __shared__ float4 xs[GROWS][16];
    const int j = threadIdx.x;           // 0..63 output column
    const int y = threadIdx.y;           // 0..3
    const int tid = y * 64 + j;
    const int row0 = blockIdx.x * GROWS;
    if (row0 >= n) return;

    float w[64];
#pragma unroll
    for (int k = 0; k < 64; k++) w[k] = W[k * 64 + j];

    const float4* X4 = FROM_B ? (g_B4 + (size_t)row0 * 16)
                              : ((const float4*)(Xin + (size_t)row0 * 64));
    const int rows = min(GROWS, n - row0);
#pragma unroll
    for (int t = tid; t < GROWS * 16; t += 256) {
        int r = t >> 4;
        if (r < rows) xs[r][t & 15] = X4[t];
    }
    __syncthreads();

    float* O = (float*)g_A4;
#pragma unroll
    for (int rr = 0; rr < 8; rr++) {
        int lr = y + rr * 4;
        if (lr >= rows) continue;
        float acc = 0.0f;
#pragma unroll
        for (int kk = 0; kk < 16; kk++) {
            float4 xv = xs[lr][kk];
            acc += xv.x * w[4 * kk + 0];
            acc += xv.y * w[4 * kk + 1];
            acc += xv.z * w[4 * kk + 2];
            acc += xv.w * w[4 * kk + 3];
        }
        O[(size_t)(row0 + lr) * 64 + j] = acc;
    }
}

// ---------------- fused aggregation: gather + self-loop + bias + relu ----------
// g_B4[node] = relu(bias + dinv[node]^2 * g_A4[node] + sum_e norm_e * g_A4[src_e])
// Warp per node; lane owns channels [2*lane, 2*lane+1].
__global__ __launch_bounds__(256) void agg_k(const float* __restrict__ bias, int n) {
    int node = blockIdx.x * 8 + (threadIdx.x >> 5);
    if (node >= n) return;
    int lane = threadIdx.x & 31;
    const float2* A2 = (const float2*)g_A4;

    float dv = g_dinv[node];
    float s = dv * dv;
    float2 a = A2[(size_t)node * 32 + lane];
    float accx = a.x * s, accy = a.y * s;

    int p   = g_rs[node];
    int end = min(p + g_cnt[node], EMAX);
    for (; p < end; p++) {
        int2 rec = g_edges[p];                   // uniform across warp -> broadcast
        float w = __int_as_float(rec.y);
        float2 v = A2[(size_t)rec.x * 32 + lane];
        accx += v.x * w;
        accy += v.y * w;
    }
    float b0 = bias[lane * 2], b1 = bias[lane * 2 + 1];
    float2 r;
    r.x = fmaxf(accx + b0, 0.0f);
    r.y = fmaxf(accy + b1, 0.0f);
    ((float2*)g_B4)[(size_t)node * 32 + lane] = r;
}

// ---------------- head: logits + rescue ratios ---------------------------------
__global__ void head_k(const float* __restrict__ Wn, const float* __restrict__ bn,
                       const float* __restrict__ Wr, const float* __restrict__ br,
                       float* __restrict__ rescue, int n) {
    int gid = blockIdx.x * blockDim.x + threadIdx.x;
    int row = gid >> 5;
    if (row >= n) return;
    int l = gid & 31;
    const float* hrow = (const float*)(g_B4 + (size_t)row * 16);
    float h0 = hrow[l * 2 + 0], h1 = hrow[l * 2 + 1];
    float an = h0 * Wn[l * 2] + h1 * Wn[l * 2 + 1];
    float ar = h0 * Wr[l * 2] + h1 * Wr[l * 2 + 1];
#pragma unroll
    for (int o = 16; o > 0; o >>= 1) {
        an += __shfl_xor_sync(0xFFFFFFFFu, an, o);
        ar += __shfl_xor_sync(0xFFFFFFFFu, ar, o);
    }
    if (l == 0) {
        g_logits[row] = an + bn[0];
        float z = ar + br[0];
        rescue[row] = 0.01f / (1.0f + expf(-z));   // sigmoid * RESCUE_SCALE
    }
}

// ---------------- global softmax over N ----------------------------------------
__global__ void maxpart_k(int n) {
    __shared__ float s[256];
    float m = -3.402823466e38f;
    for (int i = blockIdx.x * 256 + threadIdx.x; i < n; i += 256 * 256)
        m = fmaxf(m, g_logits[i]);
    s[threadIdx.x] = m; __syncthreads();
    for (int o = 128; o > 0; o >>= 1) {
        if (threadIdx.x < o) s[threadIdx.x] = fmaxf(s[threadIdx.x], s[threadIdx.x + o]);
        __syncthreads();
    }
    if (threadIdx.x == 0) g_pmax[blockIdx.x] = s[0];
}

__global__ void maxred_k() {
    __shared__ float s[256];
    s[threadIdx.x] = g_pmax[threadIdx.x]; __syncthreads();
    for (int o = 128; o > 0; o >>= 1) {
        if (threadIdx.x < o) s[threadIdx.x] = fmaxf(s[threadIdx.x], s[threadIdx.x + o]);
        __syncthreads();
    }
    if (threadIdx.x == 0) { g_gmax = s[0]; g_gsum = 0.0f; }
}

__global__ void expsum_k(int n) {
    __shared__ float s[256];
    float gm = g_gmax;
    float a = 0.0f;
    for (int i = blockIdx.x * 256 + threadIdx.x; i < n; i += 256 * 256) {
        float e = expf(g_logits[i] - gm);
        g_logits[i] = e;
        a += e;
    }
    s[threadIdx.x] = a; __syncthreads();
    for (int o = 128; o > 0; o >>= 1) {
        if (threadIdx.x < o) s[threadIdx.x] += s[threadIdx.x + o];
        __syncthreads();
    }
    if (threadIdx.x == 0) atomicAdd(&g_gsum, s[0]);
}

__global__ void normalize_k(float* __restrict__ out, int n) {
    float inv = 1.0f / g_gsum;
    int i = blockIdx.x * blockDim.x + threadIdx.x;
    if (i < n) out[i] = g_logits[i] * inv;
}

// ---------------- launch --------------------------------------------------------
extern "C" void kernel_launch(void* const* d_in, const int* in_sizes, int n_in,
                              void* d_out, int out_size) {
    const float* x  = (const float*)d_in[0];
    const void*  ei = d_in[1];                 // int32 or int64 — detected on device
    const float* ew = (const float*)d_in[2];
    const float* W1 = (const float*)d_in[3];
    const float* b1 = (const float*)d_in[4];
    const float* W2 = (const float*)d_in[5];
    const float* b2 = (const float*)d_in[6];
    const float* Wn = (const float*)d_in[7];
    const float* bn = (const float*)d_in[8];
    const float* Wr = (const float*)d_in[9];
    const float* br = (const float*)d_in[10];
    float* out = (float*)d_out;

    const int n = in_sizes[0] / HDIM;     // 100000
    const int E = in_sizes[2];            // 1000000

    const int T = 256;
    const int nb_n    = (n + T - 1) / T;
    const int nb_e    = (E + T - 1) / T;
    const int nb_hd   = (n * 32 + T - 1) / T;        // warp per row
    const int nb_gemm = (n + GROWS - 1) / GROWS;
    const int nb_scan = (n + 1023) / 1024;           // 98 blocks
    const int nb_agg  = (n + 7) / 8;                 // 8 nodes / block
    dim3 gemm_blk(64, 4);

    // ---- dtype probe + CSR build (shared by both layers) ----
    detect_k<<<1, 32>>>((const int*)ei);
    init_k<<<nb_n, T>>>(n);
    deg_edges_k<<<nb_e, T>>>(ei, ew, E, n);
    dinv_k<<<nb_n, T>>>(n);
    scan1_k<<<nb_scan, 1024>>>(n);
    scan2_k<<<1, 32>>>(nb_scan);
    scan3_k<<<nb_n, T>>>(n);
    fill_k<<<nb_e, T>>>(ei, ew, E, n);

    // ---- layer 1 ----
    gemm_k<false><<<nb_gemm, gemm_blk>>>(x, W1, n);
    agg_k<<<nb_agg, T>>>(b1, n);

    // ---- layer 2 ----
    gemm_k<true><<<nb_gemm, gemm_blk>>>(nullptr, W2, n);
    agg_k<<<nb_agg, T>>>(b2, n);

    // ---- heads ----
    head_k<<<nb_hd, T>>>(Wn, bn, Wr, br, out + n, n);

    // ---- softmax over all nodes -> out[0:n) ----
    maxpart_k<<<256, 256>>>(n);
    maxred_k<<<1, 256>>>();
    expsum_k<<<256, 256>>>(n);
    normalize_k<<<nb_n, T>>>(out, n);
}